// round 15
// baseline (speedup 1.0000x reference)
#include <cuda_runtime.h>
#include <cstdint>

#define K_DIM   2048
#define N_EXP   64
#define TMX     112                  // rows per CTA (7 m-tiles)
#define TK      64
#define NKT     32
#define THREADS 512
#define BWORDS  4096                 // uint32 per B stage (16KB, hi+lo frags)
#define LDL     72
#define TOPK_TEMP 2.0f

// A bf16 tiles: row stride 144B (72 bf16), 112 rows -> 16128 B per buffer
#define ABSTR   144
#define ABUF    (TMX * ABSTR)        // 16128
#define AH_OFF(s) ((s) * ABUF)                 // 0 / 16128
#define AL_DELTA  (2 * ABUF)                   // AL(s) = AH(s) + 32256
#define B_OFF(s)  (4 * ABUF + (s) * (BWORDS * 4))
#define SMEM_BYTES (4 * ABUF + 3 * BWORDS * 4) // 64512 + 49152 = 113664

__device__ uint32_t g_wfrag[NKT * BWORDS];

__device__ __forceinline__ uint32_t pack2(float f0, float f1) {
    uint32_t r;
    asm("cvt.rn.bf16x2.f32 %0, %1, %2;" : "=r"(r) : "f"(f1), "f"(f0));
    return r;
}
__device__ __forceinline__ void split2(float f0, float f1, uint32_t &h, uint32_t &l) {
    h = pack2(f0, f1);
    float h0 = __uint_as_float(h << 16);
    float h1 = __uint_as_float(h & 0xFFFF0000u);
    l = pack2(f0 - h0, f1 - h1);
}
__device__ __forceinline__ void mma16816(float *d,
                                         uint32_t a0, uint32_t a1, uint32_t a2, uint32_t a3,
                                         uint32_t b0, uint32_t b1) {
    asm volatile("mma.sync.aligned.m16n8k16.row.col.f32.bf16.bf16.f32 "
                 "{%0,%1,%2,%3}, {%4,%5,%6,%7}, {%8,%9}, {%0,%1,%2,%3};"
                 : "+f"(d[0]), "+f"(d[1]), "+f"(d[2]), "+f"(d[3])
                 : "r"(a0), "r"(a1), "r"(a2), "r"(a3), "r"(b0), "r"(b1));
}
__device__ __forceinline__ uint4 ldm4(uint32_t addr) {
    uint4 r;
    asm volatile("ldmatrix.sync.aligned.m8n8.x4.shared.b16 {%0,%1,%2,%3}, [%4];"
                 : "=r"(r.x), "=r"(r.y), "=r"(r.z), "=r"(r.w) : "r"(addr));
    return r;
}
__device__ __forceinline__ void sts128(uint32_t addr, uint32_t r0, uint32_t r1,
                                       uint32_t r2, uint32_t r3) {
    asm volatile("st.shared.v4.b32 [%0], {%1,%2,%3,%4};"
                 :: "r"(addr), "r"(r0), "r"(r1), "r"(r2), "r"(r3) : "memory");
}
__device__ __forceinline__ void cp16(uint32_t dst, const void* src) {
    asm volatile("cp.async.cg.shared.global [%0], [%1], 16;" :: "r"(dst), "l"(src));
}

__global__ __launch_bounds__(256)
void dhr_wprep_kernel(const float* __restrict__ w)
{
    const int kt = blockIdx.x;
    const int t  = threadIdx.x;
    const int bp  = t & 31;
    const int bks = bp >> 3;
    const int brg = (bp >> 2) & 1;
    const int bn0 = t >> 5;
    const int bln = (bn0 << 2) | (bp & 3);
    const float* pW = w + bn0 * K_DIM + kt * TK + 2 * bp;
    uint32_t* dst0 = g_wfrag + kt * BWORDS;
    #pragma unroll
    for (int i = 0; i < 8; i++) {
        float2 wv = *(const float2*)(pW + i * 8 * K_DIM);
        uint32_t h, l; split2(wv.x, wv.y, h, l);
        uint32_t* d = dst0 + (((bks * 8 + i) * 32 + bln) << 2);
        d[brg] = h; d[2 + brg] = l;
    }
}

__global__ __launch_bounds__(THREADS, 1)
void dhr_ldm_kernel(const float* __restrict__ x,
                    const float* __restrict__ bias,
                    const int*   __restrict__ mat,
                    float* __restrict__ out, long rowsTotal)
{
    extern __shared__ __align__(16) char smc[];
    const uint32_t sb = (uint32_t)__cvta_generic_to_shared(smc);

    const int t    = threadIdx.x;
    const int wid  = t >> 5;
    const int lane = t & 31;
    const int q    = lane & 3;
    const int g    = lane >> 2;
    const int kh   = wid & 1;
    const int nH   = (wid >> 1) & 1;
    const int ws   = wid >> 2;
    const int two  = (ws < 3);
    const long rowBase = (long)blockIdx.x * TMX;

    // convert mapping: 448 threads, each 1 row x 16 cols
    const bool doConv = (t < 448);
    const int  crow = t >> 2;
    const int  cqc  = t & 3;
    long grow = rowBase + crow;
    if (grow > rowsTotal - 1) grow = rowsTotal - 1;
    const float* gsrc = x + grow * K_DIM + cqc * 16;

    // ldmatrix lane address pieces
    const int lrow = (lane & 7) + ((lane >> 3) & 1) * 8;
    const int lseg = ((lane >> 4) & 1) * 16;

    float acc[2][4][4];
    #pragma unroll
    for (int m = 0; m < 2; m++)
        #pragma unroll
        for (int j = 0; j < 4; j++)
            acc[m][j][0] = acc[m][j][1] = acc[m][j][2] = acc[m][j][3] = 0.f;

    float4 pf[4];

    // ---- prologue ----
    if (doConv) {
        #pragma unroll
        for (int i = 0; i < 4; i++) pf[i] = *(const float4*)(gsrc + i * 4);
        uint32_t h[8], l[8];
        #pragma unroll
        for (int p = 0; p < 4; p++) {
            split2(pf[p].x, pf[p].y, h[2*p],   l[2*p]);
            split2(pf[p].z, pf[p].w, h[2*p+1], l[2*p+1]);
        }
        uint32_t dst = sb + AH_OFF(0) + crow * ABSTR + cqc * 32;
        sts128(dst,      h[0], h[1], h[2], h[3]);
        sts128(dst + 16, h[4], h[5], h[6], h[7]);
        sts128(dst + AL_DELTA,      l[0], l[1], l[2], l[3]);
        sts128(dst + AL_DELTA + 16, l[4], l[5], l[6], l[7]);
        #pragma unroll
        for (int i = 0; i < 4; i++) pf[i] = *(const float4*)(gsrc + TK + i * 4);
    }
    #pragma unroll
    for (int s0 = 0; s0 < 2; s0++) {
        #pragma unroll
        for (int ss = 0; ss < 2; ss++) {
            int idx = ss * THREADS + t;     // 0..1023 uint4 chunks
            cp16(sb + B_OFF(s0) + idx * 16, g_wfrag + s0 * BWORDS + idx * 4);
        }
        asm volatile("cp.async.commit_group;");
    }
    asm volatile("cp.async.wait_group %0;" :: "n"(1));
    __syncthreads();

    // rotating byte offsets
    uint32_t aRd = AH_OFF(0), aWr = AH_OFF(1);
    uint32_t bCur = B_OFF(0), bNxt = B_OFF(1), bN2 = B_OFF(2);

    // ---- mainloop ----
    for (int kt = 0; kt < NKT; kt++) {
        // MMA phase: A via ldmatrix from aRd, B from bCur
        #pragma unroll
        for (int kk = 0; kk < 2; kk++) {
            const int ks = kh * 2 + kk;
            uint32_t abase = sb + aRd + (ws * 16 + lrow) * ABSTR + ks * 32 + lseg;
            uint4 ah0 = ldm4(abase);
            uint4 al0 = ldm4(abase + AL_DELTA);
            uint4 ah1, al1;
            if (two) {
                ah1 = ldm4(abase + 64 * ABSTR);
                al1 = ldm4(abase + 64 * ABSTR + AL_DELTA);
            }
            #pragma unroll
            for (int j = 0; j < 4; j++) {
                const uint4 bf = *(const uint4*)(smc + bCur +
                                   (((ks * 8 + nH * 4 + j) * 32 + lane) << 4));
                mma16816(acc[0][j], ah0.x, ah0.y, ah0.z, ah0.w, bf.x, bf.y);
                mma16816(acc[0][j], ah0.x, ah0.y, ah0.z, ah0.w, bf.z, bf.w);
                mma16816(acc[0][j], al0.x, al0.y, al0.z, al0.w, bf.x, bf.y);
                if (two) {
                    mma16816(acc[1][j], ah1.x, ah1.y, ah1.z, ah1.w, bf.x, bf.y);
                    mma16816(acc[1][j], ah1.x, ah1.y, ah1.z, ah1.w, bf.z, bf.w);
                    mma16816(acc[1][j], al1.x, al1.y, al1.z, al1.w, bf.x, bf.y);
                }
            }
        }

        // convert tile kt+1 into aWr (pf holds tile kt+1 data)
        if (doConv && kt + 1 < NKT) {
            uint32_t h[8], l[8];
            #pragma unroll
            for (int p = 0; p < 4; p++) {
                split2(pf[p].x, pf[p].y, h[2*p],   l[2*p]);
                split2(pf[p].z, pf[p].w, h[2*p+1], l[2*p+1]);
            }
            uint32_t dst = sb + aWr + crow * ABSTR + cqc * 32;
            sts128(dst,      h[0], h[1], h[2], h[3]);
            sts128(dst + 16, h[4], h[5], h[6], h[7]);
            sts128(dst + AL_DELTA,      l[0], l[1], l[2], l[3]);
            sts128(dst + AL_DELTA + 16, l[4], l[5], l[6], l[7]);
        }
        // prefetch tile kt+2 from gmem
        if (doConv && kt + 2 < NKT) {
            #pragma unroll
            for (int i = 0; i < 4; i++)
                pf[i] = *(const float4*)(gsrc + (kt + 2) * TK + i * 4);
        }
        // B stage kt+2 via cp.async
        if (kt + 2 < NKT) {
            #pragma unroll
            for (int ss = 0; ss < 2; ss++) {
                int idx = ss * THREADS + t;
                cp16(sb + bN2 + idx * 16, g_wfrag + (kt + 2) * BWORDS + idx * 4);
            }
        }
        asm volatile("cp.async.commit_group;");
        asm volatile("cp.async.wait_group %0;" :: "n"(1));
        __syncthreads();

        // rotate buffers
        uint32_t tmpa = aRd; aRd = aWr; aWr = tmpa;
        uint32_t tmpb = bCur; bCur = bNxt; bNxt = bN2; bN2 = tmpb;
    }

    // ---- epilogue: combine kh halves + bias into SMEM logits ----
    float* L = (float*)smc;
    if (kh == 0) {
        #pragma unroll
        for (int m = 0; m < 2; m++) {
            if (m == 0 || two) {
                #pragma unroll
                for (int j = 0; j < 4; j++) {
                    int c = (nH * 4 + j) * 8 + 2 * q;
                    float b0 = __ldg(&bias[c]);
                    float b1 = __ldg(&bias[c + 1]);
                    int r0 = (ws + 4 * m) * 16 + g;
                    L[r0 * LDL + c]           = acc[m][j][0] + b0;
                    L[r0 * LDL + c + 1]       = acc[m][j][1] + b1;
                    L[(r0 + 8) * LDL + c]     = acc[m][j][2] + b0;
                    L[(r0 + 8) * LDL + c + 1] = acc[m][j][3] + b1;
                }
            }
        }
    }
    __syncthreads();
    if (kh == 1) {
        #pragma unroll
        for (int m = 0; m < 2; m++) {
            if (m == 0 || two) {
                #pragma unroll
                for (int j = 0; j < 4; j++) {
                    int c = (nH * 4 + j) * 8 + 2 * q;
                    int r0 = (ws + 4 * m) * 16 + g;
                    L[r0 * LDL + c]           += acc[m][j][0];
                    L[r0 * LDL + c + 1]       += acc[m][j][1];
                    L[(r0 + 8) * LDL + c]     += acc[m][j][2];
                    L[(r0 + 8) * LDL + c + 1] += acc[m][j][3];
                }
            }
        }
    }
    __syncthreads();

    // ---- routing: one thread per row ----
    if (t < TMX) {
        bool any_immature = false;
        #pragma unroll 8
        for (int e = 0; e < N_EXP; e++)
            any_immature |= (__ldg(&mat[e]) == 0);

        float* row = &L[t * LDL];
        if (!any_immature) {
            float v1 = -__int_as_float(0x7f800000), v2 = v1;
            int i1 = 0, i2 = 0;
            #pragma unroll 8
            for (int e = 0; e < N_EXP; e++) {
                float v = row[e];
                if (v > v1)      { v2 = v1; i2 = i1; v1 = v; i1 = e; }
                else if (v > v2) { v2 = v;  i2 = e; }
            }
            float e2  = __expf(v2 - v1);
            float inv = 1.0f / (1.0f + e2);
            #pragma unroll 8
            for (int e = 0; e < N_EXP; e++) row[e] = 0.0f;
            row[i1] = inv;
            row[i2] = e2 * inv;
        } else {
            float m = -__int_as_float(0x7f800000);
            #pragma unroll 8
            for (int e = 0; e < N_EXP; e++) m = fmaxf(m, row[e]);
            float s = 0.0f;
            float tmp[N_EXP];
            #pragma unroll 8
            for (int e = 0; e < N_EXP; e++) {
                float v = __expf((row[e] - m) * (1.0f / TOPK_TEMP));
                tmp[e] = v; s += v;
            }
            float invs = 1.0f / s;
            #pragma unroll 8
            for (int e = 0; e < N_EXP; e++) row[e] = tmp[e] * invs;
        }
    }
    __syncthreads();

    // ---- coalesced float4 store (guard rows beyond rowsTotal) ----
    #pragma unroll
    for (int ss = 0; ss < 4; ss++) {
        int idx = ss * THREADS + t;
        if (idx < TMX * 16) {
            int r = idx >> 4;
            int c = (idx & 15) << 2;
            if (rowBase + r < rowsTotal) {
                float4 v = *(const float4*)&L[r * LDL + c];
                *(float4*)(out + (rowBase + r) * N_EXP + c) = v;
            }
        }
    }
}

extern "C" void kernel_launch(void* const* d_in, const int* in_sizes, int n_in,
                              void* d_out, int out_size)
{
    const float* x   = (const float*)d_in[0];   // [16384, 2048]
    const float* w   = (const float*)d_in[1];   // [64, 2048]
    const float* b   = (const float*)d_in[2];   // [64]
    const int*   mat = (const int*)  d_in[3];   // [64]
    float* out = (float*)d_out;                 // [16384, 64]

    const long ROWS = in_sizes[0] / K_DIM;      // 16384
    const int  grid = (int)((ROWS + TMX - 1) / TMX);   // 147

    cudaFuncSetAttribute(dhr_ldm_kernel,
                         cudaFuncAttributeMaxDynamicSharedMemorySize, SMEM_BYTES);

    dhr_wprep_kernel<<<NKT, 256>>>(w);
    dhr_ldm_kernel<<<grid, THREADS, SMEM_BYTES>>>(x, b, mat, out, ROWS);
}